// round 1
// baseline (speedup 1.0000x reference)
#include <cuda_runtime.h>

#define NINST 64
#define HDIM 100
#define WDIM 152
#define HW 15200
#define NB 32
#define NKP 17
#define ATTN_LEN 2737
#define KDIM 2304

// attns scratch (64 * 2737 floats = ~700 KB)
__device__ float g_attns[NINST * ATTN_LEN];

// ---------------------------------------------------------------------------
// Kernel A: attns[n][j] = sum_k top_feats[n][k] * atten_W[j][k] + atten_b[j]
// M=64 (all n per block), BN=16 columns per block, BK=32.
// ---------------------------------------------------------------------------
__global__ __launch_bounds__(128) void gemm_attns(const float* __restrict__ A,
                                                  const float* __restrict__ Wm,
                                                  const float* __restrict__ bias) {
    __shared__ float As[32][64];   // [k][n]
    __shared__ float Ws[32][16];   // [k][j]
    int tid = threadIdx.x;
    int jblk = blockIdx.x * 16;

    int an = tid >> 1;           // 0..63  (row of A)
    int ak = (tid & 1) * 16;     // 0 or 16 (k offset within tile)
    int wj = tid >> 3;           // 0..15  (col j within tile)
    int wk = (tid & 7) * 4;      // 0..28

    int n0 = (tid & 15) * 4;     // thread micro-tile: 4 n
    int j0 = (tid >> 4) * 2;     // 2 j

    float acc[4][2];
#pragma unroll
    for (int i = 0; i < 4; i++) { acc[i][0] = 0.f; acc[i][1] = 0.f; }

    for (int k0 = 0; k0 < KDIM; k0 += 32) {
        __syncthreads();
        // Load A tile (transposed into [k][n])
        const float4* ap = (const float4*)(A + (size_t)an * KDIM + k0 + ak);
#pragma unroll
        for (int v = 0; v < 4; v++) {
            float4 t = ap[v];
            As[ak + v * 4 + 0][an] = t.x;
            As[ak + v * 4 + 1][an] = t.y;
            As[ak + v * 4 + 2][an] = t.z;
            As[ak + v * 4 + 3][an] = t.w;
        }
        // Load W tile (transposed into [k][j]), guard j bound
        {
            int j = jblk + wj;
            float4 t = make_float4(0.f, 0.f, 0.f, 0.f);
            if (j < ATTN_LEN)
                t = *(const float4*)(Wm + (size_t)j * KDIM + k0 + wk);
            Ws[wk + 0][wj] = t.x;
            Ws[wk + 1][wj] = t.y;
            Ws[wk + 2][wj] = t.z;
            Ws[wk + 3][wj] = t.w;
        }
        __syncthreads();
#pragma unroll
        for (int kk = 0; kk < 32; kk++) {
            float4 a = *(const float4*)&As[kk][n0];
            float2 w = *(const float2*)&Ws[kk][j0];
            acc[0][0] += a.x * w.x; acc[0][1] += a.x * w.y;
            acc[1][0] += a.y * w.x; acc[1][1] += a.y * w.y;
            acc[2][0] += a.z * w.x; acc[2][1] += a.z * w.y;
            acc[3][0] += a.w * w.x; acc[3][1] += a.w * w.y;
        }
    }
#pragma unroll
    for (int dn = 0; dn < 4; dn++) {
#pragma unroll
        for (int dj = 0; dj < 2; dj++) {
            int j = jblk + j0 + dj;
            if (j < ATTN_LEN)
                g_attns[(size_t)(n0 + dn) * ATTN_LEN + j] = acc[dn][dj] + bias[j];
        }
    }
}

// ---------------------------------------------------------------------------
// Kernel B: per-(instance, pixel) MLP 34 -> 32 -> 32 -> 17, writes logits.
// One block = (pixel tile of 256, instance). Weights in smem (transposed for
// broadcast LDS.128). h1/h2 staged via per-thread smem columns so all outer
// c-loops stay rolled (small code, ~60 regs).
// ---------------------------------------------------------------------------
__device__ __forceinline__ void accum32(float* h, const float* w, float xv) {
#pragma unroll
    for (int o4 = 0; o4 < 8; o4++) {
        float4 ww = *(const float4*)(w + o4 * 4);
        h[o4 * 4 + 0] += ww.x * xv;
        h[o4 * 4 + 1] += ww.y * xv;
        h[o4 * 4 + 2] += ww.z * xv;
        h[o4 * 4 + 3] += ww.w * xv;
    }
}

__global__ __launch_bounds__(256) void mlp_kernel(const float* __restrict__ bases_full,
                                                  const float* __restrict__ locations,
                                                  const float* __restrict__ sizes,
                                                  const int* __restrict__ fpn_levels,
                                                  float* __restrict__ out) {
    // smem layout (floats): w0t[1088] | w1t[1024] | w2t[640 (stride 20)] |
    //                       b0[32] | b1[32] | b2[17+3 pad] | hs[32*256]
    __shared__ float sm[2836 + 32 * 256];
    float* w0t = sm;
    float* w1t = sm + 1088;
    float* w2t = sm + 2112;
    float* b0s = sm + 2752;
    float* b1s = sm + 2784;
    float* b2s = sm + 2816;
    float* hs  = sm + 2836;

    int tid = threadIdx.x;
    int n = blockIdx.y;
    const float* row = g_attns + (size_t)n * ATTN_LEN;

    // transpose weights into smem: wXt[c*stride + o] = wX[o][c]
    for (int idx = tid; idx < 1088; idx += 256) {
        int o = idx / 34, c = idx % 34;
        w0t[c * 32 + o] = row[idx];
    }
    for (int idx = tid; idx < 1024; idx += 256) {
        int o = idx >> 5, c = idx & 31;
        w1t[c * 32 + o] = row[1120 + idx];
    }
    for (int idx = tid; idx < 544; idx += 256) {
        int o = idx >> 5, c = idx & 31;
        w2t[c * 20 + o] = row[2176 + idx];
    }
    if (tid < 32) { b0s[tid] = row[1088 + tid]; b1s[tid] = row[2144 + tid]; }
    if (tid < 17) b2s[tid] = row[2720 + tid];
    __syncthreads();

    int i = blockIdx.x * 256 + tid;
    if (i >= HW) return;

    float gx = (float)(i % WDIM) * 8.f + 4.f;
    float gy = (float)(i / WDIM) * 8.f + 4.f;
    float invr = 1.f / sizes[fpn_levels[n]];
    float ox = (locations[2 * n]     - gx) * invr;
    float oy = (locations[2 * n + 1] - gy) * invr;

    float h[32];
    // ---- layer 1 ----
#pragma unroll
    for (int o = 0; o < 32; o++) h[o] = b0s[o];
    accum32(h, w0t, ox);
    accum32(h, w0t + 32, oy);
    const float* bp = bases_full + i;
#pragma unroll 4
    for (int c = 0; c < 32; c++) {
        float xv = bp[(size_t)c * HW];
        accum32(h, w0t + (c + 2) * 32, xv);
    }
    float* hcol = hs + tid;
#pragma unroll
    for (int o = 0; o < 32; o++) hcol[o * 256] = fmaxf(h[o], 0.f);

    // ---- layer 2 ----
#pragma unroll
    for (int o = 0; o < 32; o++) h[o] = b1s[o];
#pragma unroll 4
    for (int c = 0; c < 32; c++) {
        float hv = hcol[c * 256];
        accum32(h, w1t + c * 32, hv);
    }
#pragma unroll
    for (int o = 0; o < 32; o++) hcol[o * 256] = fmaxf(h[o], 0.f);

    // ---- layer 3 (17 outputs, no relu) ----
    float lg[17];
#pragma unroll
    for (int o = 0; o < 17; o++) lg[o] = b2s[o];
#pragma unroll 4
    for (int c = 0; c < 32; c++) {
        float hv = hcol[c * 256];
        const float* w = w2t + c * 20;
#pragma unroll
        for (int o4 = 0; o4 < 4; o4++) {
            float4 ww = *(const float4*)(w + o4 * 4);
            lg[o4 * 4 + 0] += ww.x * hv;
            lg[o4 * 4 + 1] += ww.y * hv;
            lg[o4 * 4 + 2] += ww.z * hv;
            lg[o4 * 4 + 3] += ww.w * hv;
        }
        lg[16] += w[16] * hv;
    }

    float* op = out + (size_t)n * NKP * HW + i;
#pragma unroll
    for (int o = 0; o < 17; o++) op[(size_t)o * HW] = lg[o];
}

// ---------------------------------------------------------------------------
// Kernel C: per (n, kp) argmax over HW (first-index tie-break, matching
// jnp.argmax), then gather keypoint = dirmap + grid coordinate.
// ---------------------------------------------------------------------------
__global__ __launch_bounds__(128) void argmax_kernel(float* __restrict__ out,
                                                     const float* __restrict__ bases_full) {
    int pair = blockIdx.x;
    int n = pair / NKP, k = pair % NKP;
    const float4* lg = (const float4*)(out + (size_t)pair * HW);
    int tid = threadIdx.x;

    float best = -3.4e38f;
    int bi = 0;
    for (int q = tid; q < HW / 4; q += 128) {
        float4 v = lg[q];
        int i0 = q * 4;
        if (v.x > best) { best = v.x; bi = i0; }
        if (v.y > best) { best = v.y; bi = i0 + 1; }
        if (v.z > best) { best = v.z; bi = i0 + 2; }
        if (v.w > best) { best = v.w; bi = i0 + 3; }
    }

    __shared__ float sv[128];
    __shared__ int si[128];
    sv[tid] = best;
    si[tid] = bi;
    __syncthreads();
#pragma unroll
    for (int s = 64; s > 0; s >>= 1) {
        if (tid < s) {
            float ov = sv[tid + s]; int oi = si[tid + s];
            if (ov > sv[tid] || (ov == sv[tid] && oi < si[tid])) {
                sv[tid] = ov; si[tid] = oi;
            }
        }
        __syncthreads();
    }
    if (tid == 0) {
        int i = si[0];
        float gx = (float)(i % WDIM) * 8.f + 4.f;
        float gy = (float)(i / WDIM) * 8.f + 4.f;
        float* kp = out + (size_t)NINST * NKP * HW + (size_t)pair * 2;
        kp[0] = bases_full[(size_t)(NB + 2 * k)     * HW + i] + gx;
        kp[1] = bases_full[(size_t)(NB + 2 * k + 1) * HW + i] + gy;
    }
}

// ---------------------------------------------------------------------------
extern "C" void kernel_launch(void* const* d_in, const int* in_sizes, int n_in,
                              void* d_out, int out_size) {
    const float* bases_full = (const float*)d_in[0];
    const float* top_feats  = (const float*)d_in[1];
    const float* locations  = (const float*)d_in[2];
    const float* atten_W    = (const float*)d_in[3];
    const float* atten_b    = (const float*)d_in[4];
    const float* sizes      = (const float*)d_in[5];
    const int*   fpn_levels = (const int*)d_in[6];
    float* out = (float*)d_out;

    gemm_attns<<<(ATTN_LEN + 15) / 16, 128>>>(top_feats, atten_W, atten_b);

    dim3 grid((HW + 255) / 256, NINST);
    mlp_kernel<<<grid, 256>>>(bases_full, locations, sizes, fpn_levels, out);

    argmax_kernel<<<NINST * NKP, 128>>>(out, bases_full);
}

// round 2
// speedup vs baseline: 1.6226x; 1.6226x over previous
#include <cuda_runtime.h>

#define NINST 64
#define HDIM 100
#define WDIM 152
#define HW 15200
#define NB 32
#define NKP 17
#define ATTN_LEN 2737
#define KDIM 2304
#define KSPLIT 8
#define KCHUNK (KDIM / KSPLIT)   // 288

typedef unsigned long long ull;

__device__ float g_attns[NINST * ATTN_LEN];
__device__ float g_part[KSPLIT * NINST * ATTN_LEN];

// ---------------- packed f32x2 helpers ----------------
__device__ __forceinline__ ull pack2(float x, float y) {
    ull r; asm("mov.b64 %0, {%1, %2};" : "=l"(r) : "f"(x), "f"(y)); return r;
}
__device__ __forceinline__ ull ffma2(ull a, ull b, ull c) {
    ull d; asm("fma.rn.f32x2 %0, %1, %2, %3;" : "=l"(d) : "l"(a), "l"(b), "l"(c)); return d;
}
__device__ __forceinline__ float2 unpack2(ull v) {
    float2 r; asm("mov.b64 {%0, %1}, %2;" : "=f"(r.x), "=f"(r.y) : "l"(v)); return r;
}

// ---------------------------------------------------------------------------
// Kernel A1: split-K partial GEMM. grid = (172 j-tiles, 8 k-splits), 128 thr.
// Each block: 64(M) x 16(N) over K=288. Accumulators packed f32x2 over n-pairs.
// ---------------------------------------------------------------------------
__global__ __launch_bounds__(128) void gemm_partial(const float* __restrict__ A,
                                                    const float* __restrict__ Wm) {
    __shared__ __align__(16) float As[32][64];   // [k][n]
    __shared__ __align__(16) float Ws[32][16];   // [k][j]
    int tid = threadIdx.x;
    int jblk = blockIdx.x * 16;
    int kbase = blockIdx.y * KCHUNK;

    int an = tid >> 1;           // 0..63
    int ak = (tid & 1) * 16;     // 0 or 16
    int wj = tid >> 3;           // 0..15
    int wk = (tid & 7) * 4;      // 0..28
    int n0 = (tid & 15) * 4;     // 4 consecutive n (2 pairs)
    int j0 = (tid >> 4) * 2;     // 2 j

    ull acc2[2][2];
    acc2[0][0] = acc2[0][1] = acc2[1][0] = acc2[1][1] = 0ULL;

    for (int k0 = kbase; k0 < kbase + KCHUNK; k0 += 32) {
        __syncthreads();
        const float4* ap = (const float4*)(A + (size_t)an * KDIM + k0 + ak);
#pragma unroll
        for (int v = 0; v < 4; v++) {
            float4 t = ap[v];
            As[ak + v * 4 + 0][an] = t.x;
            As[ak + v * 4 + 1][an] = t.y;
            As[ak + v * 4 + 2][an] = t.z;
            As[ak + v * 4 + 3][an] = t.w;
        }
        {
            int j = jblk + wj;
            float4 t = make_float4(0.f, 0.f, 0.f, 0.f);
            if (j < ATTN_LEN)
                t = *(const float4*)(Wm + (size_t)j * KDIM + k0 + wk);
            Ws[wk + 0][wj] = t.x;
            Ws[wk + 1][wj] = t.y;
            Ws[wk + 2][wj] = t.z;
            Ws[wk + 3][wj] = t.w;
        }
        __syncthreads();
#pragma unroll
        for (int kk = 0; kk < 32; kk++) {
            ulonglong2 a2 = *(const ulonglong2*)&As[kk][n0];   // pairs (n0,n0+1),(n0+2,n0+3)
            float2 wf = *(const float2*)&Ws[kk][j0];
            ull wx = pack2(wf.x, wf.x);
            ull wy = pack2(wf.y, wf.y);
            acc2[0][0] = ffma2(a2.x, wx, acc2[0][0]);
            acc2[0][1] = ffma2(a2.x, wy, acc2[0][1]);
            acc2[1][0] = ffma2(a2.y, wx, acc2[1][0]);
            acc2[1][1] = ffma2(a2.y, wy, acc2[1][1]);
        }
    }
    float* outp = g_part + (size_t)blockIdx.y * NINST * ATTN_LEN;
#pragma unroll
    for (int p = 0; p < 2; p++) {
#pragma unroll
        for (int dj = 0; dj < 2; dj++) {
            int j = jblk + j0 + dj;
            if (j < ATTN_LEN) {
                float2 u = unpack2(acc2[p][dj]);
                outp[(size_t)(n0 + 2 * p)     * ATTN_LEN + j] = u.x;
                outp[(size_t)(n0 + 2 * p + 1) * ATTN_LEN + j] = u.y;
            }
        }
    }
}

// ---------------------------------------------------------------------------
// Kernel A2: deterministic reduce over KSPLIT partials + bias.
// ---------------------------------------------------------------------------
__global__ __launch_bounds__(256) void reduce_attns(const float* __restrict__ bias) {
    int idx = blockIdx.x * 256 + threadIdx.x;
    if (idx >= NINST * ATTN_LEN) return;
    float s = 0.f;
#pragma unroll
    for (int p = 0; p < KSPLIT; p++) s += g_part[(size_t)p * NINST * ATTN_LEN + idx];
    g_attns[idx] = s + bias[idx % ATTN_LEN];
}

// ---------------------------------------------------------------------------
// Kernel B: per-(instance, pixel) MLP 34 -> 32 -> 32 -> 17 using fma.rn.f32x2.
// 128 threads/block, 2 pixels/thread (block covers 256 pixels of one instance).
// Hidden activations live in registers; weights broadcast from smem pairs.
// ---------------------------------------------------------------------------
__device__ __forceinline__ void acc32_2(ull* a0, ull* a1, const float* w, ull x0, ull x1) {
    const ulonglong2* wp = (const ulonglong2*)w;   // 16B-aligned pair loads
#pragma unroll
    for (int q = 0; q < 8; q++) {
        ulonglong2 t = wp[q];
        a0[2 * q]     = ffma2(t.x, x0, a0[2 * q]);
        a0[2 * q + 1] = ffma2(t.y, x0, a0[2 * q + 1]);
        a1[2 * q]     = ffma2(t.x, x1, a1[2 * q]);
        a1[2 * q + 1] = ffma2(t.y, x1, a1[2 * q + 1]);
    }
}

__global__ __launch_bounds__(128, 3) void mlp_kernel(const float* __restrict__ bases_full,
                                                     const float* __restrict__ locations,
                                                     const float* __restrict__ sizes,
                                                     const int* __restrict__ fpn_levels,
                                                     float* __restrict__ out) {
    // smem floats: w0t[34*32] | w1t[32*32] | w2t[32*20] | b0[32] | b1[32] | b2[20]
    __shared__ __align__(16) float sm[2836];
    float* w0t = sm;            // [c][o], stride 32
    float* w1t = sm + 1088;     // [c][o], stride 32
    float* w2t = sm + 2112;     // [c][o], stride 20 (80B: 16B-aligned per row)
    float* b0s = sm + 2752;
    float* b1s = sm + 2784;
    float* b2s = sm + 2816;

    int tid = threadIdx.x;
    int n = blockIdx.y;
    const float* row = g_attns + (size_t)n * ATTN_LEN;

    for (int idx = tid; idx < 1088; idx += 128) {
        int o = idx / 34, c = idx % 34;
        w0t[c * 32 + o] = row[idx];
    }
    for (int idx = tid; idx < 1024; idx += 128) {
        int o = idx >> 5, c = idx & 31;
        w1t[c * 32 + o] = row[1120 + idx];
    }
    for (int idx = tid; idx < 544; idx += 128) {
        int o = idx >> 5, c = idx & 31;
        w2t[c * 20 + o] = row[2176 + idx];
    }
    if (tid < 32) { b0s[tid] = row[1088 + tid]; b1s[tid] = row[2144 + tid]; }
    if (tid < 17) b2s[tid] = row[2720 + tid];
    __syncthreads();

    int i0 = blockIdx.x * 256 + tid;
    int i1 = i0 + 128;
    bool v0 = i0 < HW, v1 = i1 < HW;
    int p0 = v0 ? i0 : HW - 1;      // clamped load indices
    int p1 = v1 ? i1 : HW - 1;

    float gx0 = (float)(p0 % WDIM) * 8.f + 4.f;
    float gy0 = (float)(p0 / WDIM) * 8.f + 4.f;
    float gx1 = (float)(p1 % WDIM) * 8.f + 4.f;
    float gy1 = (float)(p1 / WDIM) * 8.f + 4.f;
    float invr = 1.f / sizes[fpn_levels[n]];
    float lx = locations[2 * n], ly = locations[2 * n + 1];
    float ox0 = (lx - gx0) * invr, oy0 = (ly - gy0) * invr;
    float ox1 = (lx - gx1) * invr, oy1 = (ly - gy1) * invr;

    ull acc[2][16];
    {
        const ull* bp = (const ull*)b0s;
#pragma unroll
        for (int q = 0; q < 16; q++) { acc[0][q] = bp[q]; acc[1][q] = bp[q]; }
    }
    // ---- layer 1 ----
    acc32_2(acc[0], acc[1], w0t,      pack2(ox0, ox0), pack2(ox1, ox1));
    acc32_2(acc[0], acc[1], w0t + 32, pack2(oy0, oy0), pack2(oy1, oy1));
#pragma unroll 4
    for (int c = 0; c < 32; c++) {
        float xa = bases_full[(size_t)c * HW + p0];
        float xb = bases_full[(size_t)c * HW + p1];
        acc32_2(acc[0], acc[1], w0t + (c + 2) * 32, pack2(xa, xa), pack2(xb, xb));
    }
    float ha[32], hb[32];
#pragma unroll
    for (int q = 0; q < 16; q++) {
        float2 u = unpack2(acc[0][q]);
        ha[2 * q] = fmaxf(u.x, 0.f); ha[2 * q + 1] = fmaxf(u.y, 0.f);
        float2 v = unpack2(acc[1][q]);
        hb[2 * q] = fmaxf(v.x, 0.f); hb[2 * q + 1] = fmaxf(v.y, 0.f);
    }

    // ---- layer 2 (fully unrolled so h stays in registers) ----
    {
        const ull* bp = (const ull*)b1s;
#pragma unroll
        for (int q = 0; q < 16; q++) { acc[0][q] = bp[q]; acc[1][q] = bp[q]; }
    }
#pragma unroll
    for (int c = 0; c < 32; c++)
        acc32_2(acc[0], acc[1], w1t + c * 32, pack2(ha[c], ha[c]), pack2(hb[c], hb[c]));
#pragma unroll
    for (int q = 0; q < 16; q++) {
        float2 u = unpack2(acc[0][q]);
        ha[2 * q] = fmaxf(u.x, 0.f); ha[2 * q + 1] = fmaxf(u.y, 0.f);
        float2 v = unpack2(acc[1][q]);
        hb[2 * q] = fmaxf(v.x, 0.f); hb[2 * q + 1] = fmaxf(v.y, 0.f);
    }

    // ---- layer 3: 17 outputs = 8 pairs + 1 scalar ----
    ull a3[2][8];
    float a3s[2];
    {
        const ull* bp = (const ull*)b2s;
#pragma unroll
        for (int q = 0; q < 8; q++) { a3[0][q] = bp[q]; a3[1][q] = bp[q]; }
        a3s[0] = a3s[1] = b2s[16];
    }
#pragma unroll
    for (int c = 0; c < 32; c++) {
        const ulonglong2* wp = (const ulonglong2*)(w2t + c * 20);
        ull x0 = pack2(ha[c], ha[c]);
        ull x1 = pack2(hb[c], hb[c]);
#pragma unroll
        for (int q = 0; q < 4; q++) {
            ulonglong2 t = wp[q];
            a3[0][2 * q]     = ffma2(t.x, x0, a3[0][2 * q]);
            a3[0][2 * q + 1] = ffma2(t.y, x0, a3[0][2 * q + 1]);
            a3[1][2 * q]     = ffma2(t.x, x1, a3[1][2 * q]);
            a3[1][2 * q + 1] = ffma2(t.y, x1, a3[1][2 * q + 1]);
        }
        float ws = w2t[c * 20 + 16];
        a3s[0] = fmaf(ws, ha[c], a3s[0]);
        a3s[1] = fmaf(ws, hb[c], a3s[1]);
    }

    float* ob = out + (size_t)n * NKP * HW;
    if (v0) {
        float* op = ob + i0;
#pragma unroll
        for (int q = 0; q < 8; q++) {
            float2 u = unpack2(a3[0][q]);
            op[(size_t)(2 * q) * HW] = u.x;
            op[(size_t)(2 * q + 1) * HW] = u.y;
        }
        op[(size_t)16 * HW] = a3s[0];
    }
    if (v1) {
        float* op = ob + i1;
#pragma unroll
        for (int q = 0; q < 8; q++) {
            float2 u = unpack2(a3[1][q]);
            op[(size_t)(2 * q) * HW] = u.x;
            op[(size_t)(2 * q + 1) * HW] = u.y;
        }
        op[(size_t)16 * HW] = a3s[1];
    }
}

// ---------------------------------------------------------------------------
// Kernel C: per (n, kp) argmax over HW (first-index tie-break), then gather.
// ---------------------------------------------------------------------------
__global__ __launch_bounds__(256) void argmax_kernel(float* __restrict__ out,
                                                     const float* __restrict__ bases_full) {
    int pair = blockIdx.x;
    int k = pair % NKP;
    const float4* lg = (const float4*)(out + (size_t)pair * HW);
    int tid = threadIdx.x;

    float best = -3.4e38f;
    int bi = 0;
    for (int q = tid; q < HW / 4; q += 256) {
        float4 v = lg[q];
        int i0 = q * 4;
        if (v.x > best) { best = v.x; bi = i0; }
        if (v.y > best) { best = v.y; bi = i0 + 1; }
        if (v.z > best) { best = v.z; bi = i0 + 2; }
        if (v.w > best) { best = v.w; bi = i0 + 3; }
    }

    __shared__ float sv[256];
    __shared__ int si[256];
    sv[tid] = best;
    si[tid] = bi;
    __syncthreads();
#pragma unroll
    for (int s = 128; s > 0; s >>= 1) {
        if (tid < s) {
            float ov = sv[tid + s]; int oi = si[tid + s];
            if (ov > sv[tid] || (ov == sv[tid] && oi < si[tid])) {
                sv[tid] = ov; si[tid] = oi;
            }
        }
        __syncthreads();
    }
    if (tid == 0) {
        int i = si[0];
        float gx = (float)(i % WDIM) * 8.f + 4.f;
        float gy = (float)(i / WDIM) * 8.f + 4.f;
        float* kp = out + (size_t)NINST * NKP * HW + (size_t)pair * 2;
        kp[0] = bases_full[(size_t)(NB + 2 * k)     * HW + i] + gx;
        kp[1] = bases_full[(size_t)(NB + 2 * k + 1) * HW + i] + gy;
    }
}

// ---------------------------------------------------------------------------
extern "C" void kernel_launch(void* const* d_in, const int* in_sizes, int n_in,
                              void* d_out, int out_size) {
    const float* bases_full = (const float*)d_in[0];
    const float* top_feats  = (const float*)d_in[1];
    const float* locations  = (const float*)d_in[2];
    const float* atten_W    = (const float*)d_in[3];
    const float* atten_b    = (const float*)d_in[4];
    const float* sizes      = (const float*)d_in[5];
    const int*   fpn_levels = (const int*)d_in[6];
    float* out = (float*)d_out;

    gemm_partial<<<dim3((ATTN_LEN + 15) / 16, KSPLIT), 128>>>(top_feats, atten_W);
    reduce_attns<<<(NINST * ATTN_LEN + 255) / 256, 256>>>(atten_b);

    dim3 grid((HW + 255) / 256, NINST);
    mlp_kernel<<<grid, 128>>>(bases_full, locations, sizes, fpn_levels, out);

    argmax_kernel<<<NINST * NKP, 256>>>(out, bases_full);
}